// round 15
// baseline (speedup 1.0000x reference)
#include <cuda_runtime.h>
#include <cuda_bf16.h>
#include <cstdint>
#include <cstddef>

// ---------------------------------------------------------------------------
// Problem constants
// ---------------------------------------------------------------------------
#define N_NODES 100000
#define N_PAD   100096              // 782 * 128
#define N_EDGES 1600000
#define IN_C    128
#define HID     384
#define FC1     128

typedef __nv_bfloat16 bf16;

// scan partition
#define SC_T   256
#define SC_NB  ((N_NODES + SC_T - 1) / SC_T)   // 391

// ---------------------------------------------------------------------------
// Scratch (no cudaMalloc allowed). Pad rows of the h0 planes are NEVER
// written -> they stay at static zero-init across all graph replays.
// ---------------------------------------------------------------------------
__device__ bf16  g_h0h[(size_t)N_PAD * IN_C];
__device__ bf16  g_h0l[(size_t)N_PAD * IN_C];
__device__ bf16  g_h1h[(size_t)N_PAD * HID];
__device__ bf16  g_h1l[(size_t)N_PAD * HID];
__device__ bf16  g_h2h[(size_t)N_PAD * HID];
__device__ bf16  g_h2l[(size_t)N_PAD * HID];
__device__ float g_h3 [(size_t)N_PAD * FC1];
__device__ bf16  g_W1h[IN_C * HID],  g_W1l[IN_C * HID];
__device__ bf16  g_W2h[HID * HID],   g_W2l[HID * HID];
__device__ bf16  g_Wfh[HID * FC1],   g_Wfl[HID * FC1];
// CSR scatter->gather machinery
__device__ int   g_srcv[N_EDGES];
__device__ int   g_dstv[N_EDGES];
__device__ int   g_deg[N_NODES + 1];
__device__ int   g_rs [N_NODES + 1];
__device__ int   g_cur[N_NODES];
__device__ int   g_adj[N_EDGES];
__device__ int   g_bsum[SC_NB];
__device__ int   g_boff[SC_NB];
__device__ int   g_is64;

// ---------------------------------------------------------------------------
__device__ __forceinline__ float selu_f(float x) {
    const float sc = 1.0507009873554805f;
    const float al = 1.6732632423543772f;
    return x > 0.f ? sc * x : sc * al * (__expf(x) - 1.f);
}
__device__ __forceinline__ uint32_t s2u(const void* p) {
    return (uint32_t)__cvta_generic_to_shared(p);
}
__device__ __forceinline__ void cp16(void* smem_dst, const void* gmem_src) {
    asm volatile("cp.async.cg.shared.global [%0], [%1], 16;"
                 :: "r"(s2u(smem_dst)), "l"(gmem_src));
}
__device__ __forceinline__ void ldm_x4(uint32_t r[4], uint32_t addr) {
    asm volatile("ldmatrix.sync.aligned.m8n8.x4.shared.b16 {%0,%1,%2,%3}, [%4];"
                 : "=r"(r[0]), "=r"(r[1]), "=r"(r[2]), "=r"(r[3]) : "r"(addr));
}
__device__ __forceinline__ void ldm_x4_t(uint32_t r[4], uint32_t addr) {
    asm volatile("ldmatrix.sync.aligned.m8n8.x4.trans.shared.b16 {%0,%1,%2,%3}, [%4];"
                 : "=r"(r[0]), "=r"(r[1]), "=r"(r[2]), "=r"(r[3]) : "r"(addr));
}
__device__ __forceinline__ void mma_bf16(float c[4], const uint32_t a[4],
                                         const uint32_t b0, const uint32_t b1) {
    asm volatile(
        "mma.sync.aligned.m16n8k16.row.col.f32.bf16.bf16.f32 "
        "{%0,%1,%2,%3}, {%4,%5,%6,%7}, {%8,%9}, {%0,%1,%2,%3};"
        : "+f"(c[0]), "+f"(c[1]), "+f"(c[2]), "+f"(c[3])
        : "r"(a[0]), "r"(a[1]), "r"(a[2]), "r"(a[3]), "r"(b0), "r"(b1));
}

// ---------------------------------------------------------------------------
// edge dtype detect (one warp: 2 values/lane + __all_sync)
// ---------------------------------------------------------------------------
__global__ void k_detect(const void* __restrict__ ei) {
    const unsigned long long* p = (const unsigned long long*)ei;
    int lane = threadIdx.x;
    int ok = (p[lane] < (unsigned long long)N_NODES) &&
             (p[lane + 32] < (unsigned long long)N_NODES);
    ok = __all_sync(0xffffffffu, ok);
    if (lane == 0) g_is64 = ok;
}

// zero the degree histogram (needed every call; graph replays reuse state)
__global__ void k_zero() {
    int i = blockIdx.x * blockDim.x + threadIdx.x;
    if (i <= N_NODES) g_deg[i] = 0;
}

// convert edges to int32 + count in-degree per dst
__global__ void k_count(const void* __restrict__ ei) {
    int e = blockIdx.x * blockDim.x + threadIdx.x;
    if (e >= N_EDGES) return;
    long long s, d;
    if (g_is64) {
        const long long* p = (const long long*)ei;
        s = p[e]; d = p[(size_t)N_EDGES + e];
    } else {
        const int* p = (const int*)ei;
        s = p[e]; d = p[(size_t)N_EDGES + e];
    }
    int si = ((unsigned long long)s < N_NODES) ? (int)s : -1;
    int di = ((unsigned long long)d < N_NODES) ? (int)d : -1;
    g_srcv[e] = si;
    g_dstv[e] = di;
    if (si >= 0 && di >= 0) atomicAdd(&g_deg[di], 1);
}

// ---------------------------------------------------------------------------
// 3-phase parallel exclusive scan of g_deg -> g_rs (+ g_cur)
// ---------------------------------------------------------------------------
__global__ void __launch_bounds__(SC_T)
k_scan1() {
    __shared__ int sh[SC_T];
    int idx = blockIdx.x * SC_T + threadIdx.x;
    int v = (idx < N_NODES) ? g_deg[idx] : 0;
    sh[threadIdx.x] = v;
    __syncthreads();
#pragma unroll
    for (int off = SC_T / 2; off > 0; off >>= 1) {
        if (threadIdx.x < off) sh[threadIdx.x] += sh[threadIdx.x + off];
        __syncthreads();
    }
    if (threadIdx.x == 0) g_bsum[blockIdx.x] = sh[0];
}

__global__ void __launch_bounds__(512)
k_scan2() {
    __shared__ int sh[512];
    int t = threadIdx.x;
    int v = (t < SC_NB) ? g_bsum[t] : 0;
    sh[t] = v;
    __syncthreads();
#pragma unroll
    for (int off = 1; off < 512; off <<= 1) {
        int u = (t >= off) ? sh[t - off] : 0;
        __syncthreads();
        sh[t] += u;
        __syncthreads();
    }
    if (t < SC_NB) g_boff[t] = sh[t] - v;          // exclusive
    if (t == 511) g_rs[N_NODES] = sh[511];         // total edge count
}

__global__ void __launch_bounds__(SC_T)
k_scan3() {
    __shared__ int sh[SC_T];
    int idx = blockIdx.x * SC_T + threadIdx.x;
    int v = (idx < N_NODES) ? g_deg[idx] : 0;
    sh[threadIdx.x] = v;
    __syncthreads();
#pragma unroll
    for (int off = 1; off < SC_T; off <<= 1) {
        int u = (threadIdx.x >= off) ? sh[threadIdx.x - off] : 0;
        __syncthreads();
        sh[threadIdx.x] += u;
        __syncthreads();
    }
    if (idx < N_NODES) {
        int r = g_boff[blockIdx.x] + sh[threadIdx.x] - v;   // exclusive
        g_rs[idx]  = r;
        g_cur[idx] = r;
    }
}

// fill adjacency
__global__ void k_fill() {
    int e = blockIdx.x * blockDim.x + threadIdx.x;
    if (e >= N_EDGES) return;
    int si = g_srcv[e], di = g_dstv[e];
    if (si < 0 || di < 0) return;
    int pos = atomicAdd(&g_cur[di], 1);
    g_adj[pos] = si;
}

// gather: one warp per node; writes h0 hi/lo planes directly
__global__ void k_gather(const float* __restrict__ z) {
    int w = (blockIdx.x * blockDim.x + threadIdx.x) >> 5;
    if (w >= N_NODES) return;
    int lane = threadIdx.x & 31;

    float4 acc = ((const float4*)(z + (size_t)w * IN_C))[lane];
    int e   = g_rs[w];
    int end = g_rs[w + 1];
    for (; e + 1 < end; e += 2) {
        int s0 = g_adj[e], s1 = g_adj[e + 1];
        float4 v0 = ((const float4*)(z + (size_t)s0 * IN_C))[lane];
        float4 v1 = ((const float4*)(z + (size_t)s1 * IN_C))[lane];
        acc.x += v0.x + v1.x; acc.y += v0.y + v1.y;
        acc.z += v0.z + v1.z; acc.w += v0.w + v1.w;
    }
    if (e < end) {
        int s0 = g_adj[e];
        float4 v0 = ((const float4*)(z + (size_t)s0 * IN_C))[lane];
        acc.x += v0.x; acc.y += v0.y; acc.z += v0.z; acc.w += v0.w;
    }

    float xs[4] = {acc.x, acc.y, acc.z, acc.w};
    bf16 h[4], l[4];
#pragma unroll
    for (int j = 0; j < 4; j++) {
        h[j] = __float2bfloat16(xs[j]);
        l[j] = __float2bfloat16(xs[j] - __bfloat162float(h[j]));
    }
    size_t o2 = (size_t)w * (IN_C / 2) + lane * 2;
    ((__nv_bfloat162*)g_h0h)[o2]     = __nv_bfloat162(h[0], h[1]);
    ((__nv_bfloat162*)g_h0h)[o2 + 1] = __nv_bfloat162(h[2], h[3]);
    ((__nv_bfloat162*)g_h0l)[o2]     = __nv_bfloat162(l[0], l[1]);
    ((__nv_bfloat162*)g_h0l)[o2 + 1] = __nv_bfloat162(l[2], l[3]);
}

// ---------------------------------------------------------------------------
// split fp32 -> (hi, lo) bf16 planes (weights only)
// ---------------------------------------------------------------------------
__global__ void k_split(const float* __restrict__ X, bf16* __restrict__ Xh,
                        bf16* __restrict__ Xl, int n4) {
    int i = blockIdx.x * blockDim.x + threadIdx.x;
    if (i >= n4) return;
    float4 v = ((const float4*)X)[i];
    float xs[4] = {v.x, v.y, v.z, v.w};
    bf16 h[4], l[4];
#pragma unroll
    for (int j = 0; j < 4; j++) {
        h[j] = __float2bfloat16(xs[j]);
        l[j] = __float2bfloat16(xs[j] - __bfloat162float(h[j]));
    }
    ((__nv_bfloat162*)Xh)[i * 2]     = __nv_bfloat162(h[0], h[1]);
    ((__nv_bfloat162*)Xh)[i * 2 + 1] = __nv_bfloat162(h[2], h[3]);
    ((__nv_bfloat162*)Xl)[i * 2]     = __nv_bfloat162(l[0], l[1]);
    ((__nv_bfloat162*)Xl)[i * 2 + 1] = __nv_bfloat162(l[2], l[3]);
}

// ---------------------------------------------------------------------------
// Pipelined mma.sync GEMM on pre-split bf16 planes.
// BM=128, BN=64, BK=32; 256 thr = 8 warps (4m x 2n), warp tile 32x32.
// 2 CTAs/SM (118.8 KB combined smem) to fill sync/load bubbles.
// ---------------------------------------------------------------------------
#define LDA 40
#define LDB 72
#define OFF_AH 0
#define OFF_AL (128 * LDA)
#define OFF_BH (2 * 128 * LDA)
#define OFF_BL (2 * 128 * LDA + 32 * LDB)
#define STAGE  (2 * 128 * LDA + 2 * 32 * LDB)
#define SMEM_BYTES (2 * STAGE * 2)          // 59392 B

template <bool DO_SELU, bool OUT_SPLIT>
__global__ void __launch_bounds__(256, 2)
k_gemm2(const bf16* __restrict__ Ah, const bf16* __restrict__ Al,
        const bf16* __restrict__ Bh, const bf16* __restrict__ Bl,
        const float* __restrict__ bias,
        float* __restrict__ C, bf16* __restrict__ Ch, bf16* __restrict__ Cl,
        int N, int K) {
    extern __shared__ bf16 sm[];

    const int tid  = threadIdx.x;
    const int lane = tid & 31;
    const int wid  = tid >> 5;
    const int wm   = (wid & 3) * 32;
    const int wn   = (wid >> 2) * 32;
    const int m0   = blockIdx.y * 128;
    const int n0   = blockIdx.x * 64;
    const int NIT  = K / 32;

    auto load_stage = [&](int it, int buf) {
        bf16* base = sm + buf * STAGE;
        const int k0 = it * 32;
#pragma unroll
        for (int t = 0; t < 2; t++) {
            int c = tid + t * 256;
            int row = c >> 2, seg = c & 3;
            size_t g = (size_t)(m0 + row) * K + k0 + seg * 8;
            int    s = row * LDA + seg * 8;
            cp16(base + OFF_AH + s, Ah + g);
            cp16(base + OFF_AL + s, Al + g);
        }
        {
            int row = tid >> 3, seg = tid & 7;
            size_t g = (size_t)(k0 + row) * N + n0 + seg * 8;
            int    s = row * LDB + seg * 8;
            cp16(base + OFF_BH + s, Bh + g);
            cp16(base + OFF_BL + s, Bl + g);
        }
        asm volatile("cp.async.commit_group;");
    };

    float acc[2][4][4];
#pragma unroll
    for (int i = 0; i < 2; i++)
#pragma unroll
        for (int j = 0; j < 4; j++)
#pragma unroll
            for (int k = 0; k < 4; k++) acc[i][j][k] = 0.f;

    load_stage(0, 0);

    for (int it = 0; it < NIT; it++) {
        if (it + 1 < NIT) {
            load_stage(it + 1, (it + 1) & 1);
            asm volatile("cp.async.wait_group 1;");
        } else {
            asm volatile("cp.async.wait_group 0;");
        }
        __syncthreads();

        bf16* base = sm + (it & 1) * STAGE;
        bf16* pAh = base + OFF_AH;
        bf16* pAl = base + OFF_AL;
        bf16* pBh = base + OFF_BH;
        bf16* pBl = base + OFF_BL;

#pragma unroll
        for (int kk = 0; kk < 2; kk++) {
            uint32_t ah[2][4], al[2][4];
#pragma unroll
            for (int mt = 0; mt < 2; mt++) {
                int row  = wm + mt * 16 + (lane & 15);
                int kofs = kk * 16 + (lane >> 4) * 8;
                ldm_x4(ah[mt], s2u(pAh + row * LDA + kofs));
                ldm_x4(al[mt], s2u(pAl + row * LDA + kofs));
            }
#pragma unroll
            for (int ng = 0; ng < 2; ng++) {
                uint32_t bh[4], bl[4];
                int krow = kk * 16 + (lane & 15);
                int ncol = wn + ng * 16 + (lane >> 4) * 8;
                ldm_x4_t(bh, s2u(pBh + krow * LDB + ncol));
                ldm_x4_t(bl, s2u(pBl + krow * LDB + ncol));
#pragma unroll
                for (int mt = 0; mt < 2; mt++) {
#pragma unroll
                    for (int nn = 0; nn < 2; nn++) {
                        float* cc = acc[mt][ng * 2 + nn];
                        mma_bf16(cc, ah[mt], bh[nn * 2], bh[nn * 2 + 1]);
                        mma_bf16(cc, ah[mt], bl[nn * 2], bl[nn * 2 + 1]);
                        mma_bf16(cc, al[mt], bh[nn * 2], bh[nn * 2 + 1]);
                    }
                }
            }
        }
        __syncthreads();
    }

    const int rbase = m0 + wm + (lane >> 2);
    const int cbase = n0 + wn + (lane & 3) * 2;
#pragma unroll
    for (int mt = 0; mt < 2; mt++) {
#pragma unroll
        for (int nt = 0; nt < 4; nt++) {
            int row = rbase + mt * 16;
            int col = cbase + nt * 8;
            float b0 = bias[col], b1 = bias[col + 1];
            float v[2][2] = {{acc[mt][nt][0] + b0, acc[mt][nt][1] + b1},
                             {acc[mt][nt][2] + b0, acc[mt][nt][3] + b1}};
#pragma unroll
            for (int r = 0; r < 2; r++) {
                if (DO_SELU) { v[r][0] = selu_f(v[r][0]); v[r][1] = selu_f(v[r][1]); }
                size_t o = (size_t)(row + r * 8) * N + col;
                if (OUT_SPLIT) {
                    bf16 h0 = __float2bfloat16(v[r][0]);
                    bf16 h1 = __float2bfloat16(v[r][1]);
                    bf16 l0 = __float2bfloat16(v[r][0] - __bfloat162float(h0));
                    bf16 l1 = __float2bfloat16(v[r][1] - __bfloat162float(h1));
                    *(__nv_bfloat162*)(Ch + o) = __nv_bfloat162(h0, h1);
                    *(__nv_bfloat162*)(Cl + o) = __nv_bfloat162(l0, l1);
                } else {
                    *(float2*)(C + o) = make_float2(v[r][0], v[r][1]);
                }
            }
        }
    }
}

// ---------------------------------------------------------------------------
// final head
// ---------------------------------------------------------------------------
__global__ void k_out(const float* __restrict__ Wf2,
                      const float* __restrict__ bf2,
                      float* __restrict__ out) {
    int w = (blockIdx.x * blockDim.x + threadIdx.x) >> 5;
    if (w >= N_NODES) return;
    int lane = threadIdx.x & 31;
    float4 h  = *(const float4*)(g_h3 + (size_t)w * FC1 + lane * 4);
    float4 wt = *(const float4*)(Wf2 + lane * 4);
    float s = h.x * wt.x + h.y * wt.y + h.z * wt.z + h.w * wt.w;
#pragma unroll
    for (int off = 16; off; off >>= 1) s += __shfl_xor_sync(0xffffffffu, s, off);
    if (lane == 0) out[w] = s + bf2[0];
}

// ---------------------------------------------------------------------------
// Launch. Inputs identified by element count (proven).
// ---------------------------------------------------------------------------
extern "C" void kernel_launch(void* const* d_in, const int* in_sizes, int n_in,
                              void* d_out, int out_size) {
    const float* z  = nullptr;
    const float* W1 = nullptr, *b1 = nullptr, *W2 = nullptr, *b2 = nullptr;
    const float* Wf1 = nullptr, *bf1 = nullptr, *Wf2 = nullptr, *bf2 = nullptr;
    const void*  ei = nullptr;

    int n49152 = 0, n384 = 0, n128 = 0;
    for (int i = 0; i < n_in; i++) {
        int s = in_sizes[i];
        const void* p = d_in[i];
        switch (s) {
            case 12800000: z  = (const float*)p; break;
            case 3200000:  ei = p;               break;
            case 100000:   break;
            case 147456:   W2 = (const float*)p; break;
            case 49152:
                if (n49152++ == 0) W1 = (const float*)p; else Wf1 = (const float*)p;
                break;
            case 384:
                if (n384++ == 0) b1 = (const float*)p; else b2 = (const float*)p;
                break;
            case 128:
                if (n128++ == 0) bf1 = (const float*)p; else Wf2 = (const float*)p;
                break;
            case 1:        bf2 = (const float*)p; break;
            default: break;
        }
    }
    float* out = (float*)d_out;

    float *h3;
    bf16 *h0h, *h0l, *h1h, *h1l, *h2h, *h2l;
    bf16 *W1h, *W1l, *W2h, *W2l, *Wfh, *Wfl;
    cudaGetSymbolAddress((void**)&h0h, g_h0h);
    cudaGetSymbolAddress((void**)&h0l, g_h0l);
    cudaGetSymbolAddress((void**)&h1h, g_h1h);
    cudaGetSymbolAddress((void**)&h1l, g_h1l);
    cudaGetSymbolAddress((void**)&h2h, g_h2h);
    cudaGetSymbolAddress((void**)&h2l, g_h2l);
    cudaGetSymbolAddress((void**)&h3,  g_h3);
    cudaGetSymbolAddress((void**)&W1h, g_W1h);
    cudaGetSymbolAddress((void**)&W1l, g_W1l);
    cudaGetSymbolAddress((void**)&W2h, g_W2h);
    cudaGetSymbolAddress((void**)&W2l, g_W2l);
    cudaGetSymbolAddress((void**)&Wfh, g_Wfh);
    cudaGetSymbolAddress((void**)&Wfl, g_Wfl);

    cudaFuncSetAttribute(k_gemm2<true , true >, cudaFuncAttributeMaxDynamicSharedMemorySize, SMEM_BYTES);
    cudaFuncSetAttribute(k_gemm2<false, true >, cudaFuncAttributeMaxDynamicSharedMemorySize, SMEM_BYTES);
    cudaFuncSetAttribute(k_gemm2<true , false>, cudaFuncAttributeMaxDynamicSharedMemorySize, SMEM_BYTES);

    // --- weight splits first (hide their launches in the agg chain shadow)
    k_split<<<(IN_C * HID / 4 + 255) / 256, 256>>>(W1,  W1h, W1l, IN_C * HID / 4);
    k_split<<<(HID * HID / 4 + 255) / 256, 256>>>(W2,  W2h, W2l, HID * HID / 4);
    k_split<<<(HID * FC1 / 4 + 255) / 256, 256>>>(Wf1, Wfh, Wfl, HID * FC1 / 4);

    // --- aggregation: detect -> zero -> count -> scan(x3) -> fill -> gather
    k_detect<<<1, 32>>>(ei);
    k_zero  <<<(N_NODES + 256) / 256, 256>>>();
    k_count <<<(N_EDGES + 255) / 256, 256>>>(ei);
    k_scan1 <<<SC_NB, SC_T>>>();
    k_scan2 <<<1, 512>>>();
    k_scan3 <<<SC_NB, SC_T>>>();
    k_fill  <<<(N_EDGES + 255) / 256, 256>>>();
    k_gather<<<(N_NODES * 32 + 255) / 256, 256>>>(z);

    // --- MLP chain
    k_gemm2<true , true ><<<dim3(HID / 64, N_PAD / 128), 256, SMEM_BYTES>>>(
        h0h, h0l, W1h, W1l, b1, nullptr, h1h, h1l, HID, IN_C);
    k_gemm2<false, true ><<<dim3(HID / 64, N_PAD / 128), 256, SMEM_BYTES>>>(
        h1h, h1l, W2h, W2l, b2, nullptr, h2h, h2l, HID, HID);
    k_gemm2<true , false><<<dim3(FC1 / 64, N_PAD / 128), 256, SMEM_BYTES>>>(
        h2h, h2l, Wfh, Wfl, bf1, h3, nullptr, nullptr, FC1, HID);

    k_out<<<(N_NODES * 32 + 255) / 256, 256>>>(Wf2, bf2, out);
}

// round 16
// speedup vs baseline: 1.3253x; 1.3253x over previous
#include <cuda_runtime.h>
#include <cuda_fp16.h>
#include <cstdint>
#include <cstddef>

// ---------------------------------------------------------------------------
// Problem constants
// ---------------------------------------------------------------------------
#define N_NODES 100000
#define N_PAD   100096              // 782 * 128
#define N_EDGES 1600000
#define IN_C    128
#define HID     384
#define FC1     128

// scan partition
#define SC_T   256
#define SC_NB  ((N_NODES + SC_T - 1) / SC_T)   // 391

// ---------------------------------------------------------------------------
// Scratch (no cudaMalloc allowed). Pad rows of g_h0f are NEVER written ->
// they stay at static zero-init across all graph replays.
// Activations: single fp16 plane. Weights: fp16 hi/lo planes.
// ---------------------------------------------------------------------------
__device__ __half g_h0f[(size_t)N_PAD * IN_C];
__device__ __half g_h1f[(size_t)N_PAD * HID];
__device__ __half g_h2f[(size_t)N_PAD * HID];
__device__ float  g_h3 [(size_t)N_PAD * FC1];
__device__ __half g_W1h[IN_C * HID], g_W1l[IN_C * HID];
__device__ __half g_W2h[HID * HID],  g_W2l[HID * HID];
__device__ __half g_Wfh[HID * FC1],  g_Wfl[HID * FC1];
// CSR scatter->gather machinery
__device__ int    g_srcv[N_EDGES];
__device__ int    g_dstv[N_EDGES];
__device__ int    g_deg[N_NODES + 1];
__device__ int    g_rs [N_NODES + 1];
__device__ int    g_cur[N_NODES];
__device__ int    g_adj[N_EDGES];
__device__ int    g_bsum[SC_NB];
__device__ int    g_boff[SC_NB];
__device__ int    g_is64;

// ---------------------------------------------------------------------------
__device__ __forceinline__ float selu_f(float x) {
    const float sc = 1.0507009873554805f;
    const float al = 1.6732632423543772f;
    return x > 0.f ? sc * x : sc * al * (__expf(x) - 1.f);
}
__device__ __forceinline__ uint32_t s2u(const void* p) {
    return (uint32_t)__cvta_generic_to_shared(p);
}
__device__ __forceinline__ void cp16(void* smem_dst, const void* gmem_src) {
    asm volatile("cp.async.cg.shared.global [%0], [%1], 16;"
                 :: "r"(s2u(smem_dst)), "l"(gmem_src));
}
__device__ __forceinline__ void ldm_x4(uint32_t r[4], uint32_t addr) {
    asm volatile("ldmatrix.sync.aligned.m8n8.x4.shared.b16 {%0,%1,%2,%3}, [%4];"
                 : "=r"(r[0]), "=r"(r[1]), "=r"(r[2]), "=r"(r[3]) : "r"(addr));
}
__device__ __forceinline__ void ldm_x4_t(uint32_t r[4], uint32_t addr) {
    asm volatile("ldmatrix.sync.aligned.m8n8.x4.trans.shared.b16 {%0,%1,%2,%3}, [%4];"
                 : "=r"(r[0]), "=r"(r[1]), "=r"(r[2]), "=r"(r[3]) : "r"(addr));
}
// mma m16n8k16 fp16 -> f32 accumulate
__device__ __forceinline__ void mma_f16(float c[4], const uint32_t a[4],
                                        const uint32_t b0, const uint32_t b1) {
    asm volatile(
        "mma.sync.aligned.m16n8k16.row.col.f32.f16.f16.f32 "
        "{%0,%1,%2,%3}, {%4,%5,%6,%7}, {%8,%9}, {%0,%1,%2,%3};"
        : "+f"(c[0]), "+f"(c[1]), "+f"(c[2]), "+f"(c[3])
        : "r"(a[0]), "r"(a[1]), "r"(a[2]), "r"(a[3]), "r"(b0), "r"(b1));
}

// ---------------------------------------------------------------------------
// edge dtype detect (one warp)
// ---------------------------------------------------------------------------
__global__ void k_detect(const void* __restrict__ ei) {
    const unsigned long long* p = (const unsigned long long*)ei;
    int lane = threadIdx.x;
    int ok = (p[lane] < (unsigned long long)N_NODES) &&
             (p[lane + 32] < (unsigned long long)N_NODES);
    ok = __all_sync(0xffffffffu, ok);
    if (lane == 0) g_is64 = ok;
}

__global__ void k_zero() {
    int i = blockIdx.x * blockDim.x + threadIdx.x;
    if (i <= N_NODES) g_deg[i] = 0;
}

__global__ void k_count(const void* __restrict__ ei) {
    int e = blockIdx.x * blockDim.x + threadIdx.x;
    if (e >= N_EDGES) return;
    long long s, d;
    if (g_is64) {
        const long long* p = (const long long*)ei;
        s = p[e]; d = p[(size_t)N_EDGES + e];
    } else {
        const int* p = (const int*)ei;
        s = p[e]; d = p[(size_t)N_EDGES + e];
    }
    int si = ((unsigned long long)s < N_NODES) ? (int)s : -1;
    int di = ((unsigned long long)d < N_NODES) ? (int)d : -1;
    g_srcv[e] = si;
    g_dstv[e] = di;
    if (si >= 0 && di >= 0) atomicAdd(&g_deg[di], 1);
}

// ---------------------------------------------------------------------------
// 3-phase parallel exclusive scan (proven in R13)
// ---------------------------------------------------------------------------
__global__ void __launch_bounds__(SC_T)
k_scan1() {
    __shared__ int sh[SC_T];
    int idx = blockIdx.x * SC_T + threadIdx.x;
    int v = (idx < N_NODES) ? g_deg[idx] : 0;
    sh[threadIdx.x] = v;
    __syncthreads();
#pragma unroll
    for (int off = SC_T / 2; off > 0; off >>= 1) {
        if (threadIdx.x < off) sh[threadIdx.x] += sh[threadIdx.x + off];
        __syncthreads();
    }
    if (threadIdx.x == 0) g_bsum[blockIdx.x] = sh[0];
}

__global__ void __launch_bounds__(512)
k_scan2() {
    __shared__ int sh[512];
    int t = threadIdx.x;
    int v = (t < SC_NB) ? g_bsum[t] : 0;
    sh[t] = v;
    __syncthreads();
#pragma unroll
    for (int off = 1; off < 512; off <<= 1) {
        int u = (t >= off) ? sh[t - off] : 0;
        __syncthreads();
        sh[t] += u;
        __syncthreads();
    }
    if (t < SC_NB) g_boff[t] = sh[t] - v;
    if (t == 511) g_rs[N_NODES] = sh[511];
}

__global__ void __launch_bounds__(SC_T)
k_scan3() {
    __shared__ int sh[SC_T];
    int idx = blockIdx.x * SC_T + threadIdx.x;
    int v = (idx < N_NODES) ? g_deg[idx] : 0;
    sh[threadIdx.x] = v;
    __syncthreads();
#pragma unroll
    for (int off = 1; off < SC_T; off <<= 1) {
        int u = (threadIdx.x >= off) ? sh[threadIdx.x - off] : 0;
        __syncthreads();
        sh[threadIdx.x] += u;
        __syncthreads();
    }
    if (idx < N_NODES) {
        int r = g_boff[blockIdx.x] + sh[threadIdx.x] - v;
        g_rs[idx]  = r;
        g_cur[idx] = r;
    }
}

__global__ void k_fill() {
    int e = blockIdx.x * blockDim.x + threadIdx.x;
    if (e >= N_EDGES) return;
    int si = g_srcv[e], di = g_dstv[e];
    if (si < 0 || di < 0) return;
    int pos = atomicAdd(&g_cur[di], 1);
    g_adj[pos] = si;
}

// gather: one warp per node; writes h0 single-fp16 plane directly
__global__ void k_gather(const float* __restrict__ z) {
    int w = (blockIdx.x * blockDim.x + threadIdx.x) >> 5;
    if (w >= N_NODES) return;
    int lane = threadIdx.x & 31;

    float4 acc = ((const float4*)(z + (size_t)w * IN_C))[lane];
    int e   = g_rs[w];
    int end = g_rs[w + 1];
    for (; e + 1 < end; e += 2) {
        int s0 = g_adj[e], s1 = g_adj[e + 1];
        float4 v0 = ((const float4*)(z + (size_t)s0 * IN_C))[lane];
        float4 v1 = ((const float4*)(z + (size_t)s1 * IN_C))[lane];
        acc.x += v0.x + v1.x; acc.y += v0.y + v1.y;
        acc.z += v0.z + v1.z; acc.w += v0.w + v1.w;
    }
    if (e < end) {
        int s0 = g_adj[e];
        float4 v0 = ((const float4*)(z + (size_t)s0 * IN_C))[lane];
        acc.x += v0.x; acc.y += v0.y; acc.z += v0.z; acc.w += v0.w;
    }

    size_t o2 = (size_t)w * (IN_C / 2) + lane * 2;   // half2 index
    ((__half2*)g_h0f)[o2]     = __floats2half2_rn(acc.x, acc.y);
    ((__half2*)g_h0f)[o2 + 1] = __floats2half2_rn(acc.z, acc.w);
}

// ---------------------------------------------------------------------------
// weight split fp32 -> (hi, lo) fp16 planes
// ---------------------------------------------------------------------------
__global__ void k_split(const float* __restrict__ X, __half* __restrict__ Xh,
                        __half* __restrict__ Xl, int n4) {
    int i = blockIdx.x * blockDim.x + threadIdx.x;
    if (i >= n4) return;
    float4 v = ((const float4*)X)[i];
    float xs[4] = {v.x, v.y, v.z, v.w};
    __half h[4], l[4];
#pragma unroll
    for (int j = 0; j < 4; j++) {
        h[j] = __float2half_rn(xs[j]);
        l[j] = __float2half_rn(xs[j] - __half2float(h[j]));
    }
    ((__half2*)Xh)[i * 2]     = __halves2half2(h[0], h[1]);
    ((__half2*)Xh)[i * 2 + 1] = __halves2half2(h[2], h[3]);
    ((__half2*)Xl)[i * 2]     = __halves2half2(l[0], l[1]);
    ((__half2*)Xl)[i * 2 + 1] = __halves2half2(l[2], l[3]);
}

// ---------------------------------------------------------------------------
// Pipelined mma.sync GEMM, fp16 one-sided split:
//   C = A(fp16) @ (Bh + Bl) + bias  (+SELU)
// BM=128, BN=64, BK=32; 256 thr = 8 warps (4m x 2n), warp tile 32x32.
// 2-stage cp.async; smem 38.9 KB/CTA -> 2 CTAs/SM.
// ---------------------------------------------------------------------------
#define LDA 40
#define LDB 72
#define OFF_A  0
#define OFF_BH (128 * LDA)                    // 5120
#define OFF_BL (128 * LDA + 32 * LDB)         // 7424
#define STAGE  (128 * LDA + 2 * 32 * LDB)     // 9728 halves
#define SMEM_BYTES (2 * STAGE * 2)            // 38912 B

template <bool DO_SELU, bool OUT_HALF>
__global__ void __launch_bounds__(256, 2)
k_gemm2(const __half* __restrict__ A,
        const __half* __restrict__ Bh, const __half* __restrict__ Bl,
        const float* __restrict__ bias,
        float* __restrict__ C, __half* __restrict__ Ch,
        int N, int K) {
    extern __shared__ __half sm[];

    const int tid  = threadIdx.x;
    const int lane = tid & 31;
    const int wid  = tid >> 5;
    const int wm   = (wid & 3) * 32;
    const int wn   = (wid >> 2) * 32;
    const int m0   = blockIdx.y * 128;
    const int n0   = blockIdx.x * 64;
    const int NIT  = K / 32;

    auto load_stage = [&](int it, int buf) {
        __half* base = sm + buf * STAGE;
        const int k0 = it * 32;
        // A: 128x32 half = 512 16B-chunks, 2 per thread
#pragma unroll
        for (int t = 0; t < 2; t++) {
            int c = tid + t * 256;
            int row = c >> 2, seg = c & 3;
            cp16(base + OFF_A + row * LDA + seg * 8,
                 A + (size_t)(m0 + row) * K + k0 + seg * 8);
        }
        // B planes: 32x64 half = 256 chunks each; thread handles same slot in both
        {
            int row = tid >> 3, seg = tid & 7;
            size_t g = (size_t)(k0 + row) * N + n0 + seg * 8;
            int    s = row * LDB + seg * 8;
            cp16(base + OFF_BH + s, Bh + g);
            cp16(base + OFF_BL + s, Bl + g);
        }
        asm volatile("cp.async.commit_group;");
    };

    float acc[2][4][4];
#pragma unroll
    for (int i = 0; i < 2; i++)
#pragma unroll
        for (int j = 0; j < 4; j++)
#pragma unroll
            for (int k = 0; k < 4; k++) acc[i][j][k] = 0.f;

    load_stage(0, 0);

    for (int it = 0; it < NIT; it++) {
        if (it + 1 < NIT) {
            load_stage(it + 1, (it + 1) & 1);
            asm volatile("cp.async.wait_group 1;");
        } else {
            asm volatile("cp.async.wait_group 0;");
        }
        __syncthreads();

        __half* base = sm + (it & 1) * STAGE;
        __half* pA  = base + OFF_A;
        __half* pBh = base + OFF_BH;
        __half* pBl = base + OFF_BL;

#pragma unroll
        for (int kk = 0; kk < 2; kk++) {
            uint32_t a[2][4];
#pragma unroll
            for (int mt = 0; mt < 2; mt++) {
                int row  = wm + mt * 16 + (lane & 15);
                int kofs = kk * 16 + (lane >> 4) * 8;
                ldm_x4(a[mt], s2u(pA + row * LDA + kofs));
            }
#pragma unroll
            for (int ng = 0; ng < 2; ng++) {
                uint32_t bh[4], bl[4];
                int krow = kk * 16 + (lane & 15);
                int ncol = wn + ng * 16 + (lane >> 4) * 8;
                ldm_x4_t(bh, s2u(pBh + krow * LDB + ncol));
                ldm_x4_t(bl, s2u(pBl + krow * LDB + ncol));
#pragma unroll
                for (int mt = 0; mt < 2; mt++) {
#pragma unroll
                    for (int nn = 0; nn < 2; nn++) {
                        float* cc = acc[mt][ng * 2 + nn];
                        mma_f16(cc, a[mt], bh[nn * 2], bh[nn * 2 + 1]);
                        mma_f16(cc, a[mt], bl[nn * 2], bl[nn * 2 + 1]);
                    }
                }
            }
        }
        __syncthreads();
    }

    const int rbase = m0 + wm + (lane >> 2);
    const int cbase = n0 + wn + (lane & 3) * 2;
#pragma unroll
    for (int mt = 0; mt < 2; mt++) {
#pragma unroll
        for (int nt = 0; nt < 4; nt++) {
            int row = rbase + mt * 16;
            int col = cbase + nt * 8;
            float b0 = bias[col], b1 = bias[col + 1];
            float v[2][2] = {{acc[mt][nt][0] + b0, acc[mt][nt][1] + b1},
                             {acc[mt][nt][2] + b0, acc[mt][nt][3] + b1}};
#pragma unroll
            for (int r = 0; r < 2; r++) {
                if (DO_SELU) { v[r][0] = selu_f(v[r][0]); v[r][1] = selu_f(v[r][1]); }
                size_t o = (size_t)(row + r * 8) * N + col;
                if (OUT_HALF) {
                    *(__half2*)(Ch + o) = __floats2half2_rn(v[r][0], v[r][1]);
                } else {
                    *(float2*)(C + o) = make_float2(v[r][0], v[r][1]);
                }
            }
        }
    }
}

// ---------------------------------------------------------------------------
// final head
// ---------------------------------------------------------------------------
__global__ void k_out(const float* __restrict__ Wf2,
                      const float* __restrict__ bf2,
                      float* __restrict__ out) {
    int w = (blockIdx.x * blockDim.x + threadIdx.x) >> 5;
    if (w >= N_NODES) return;
    int lane = threadIdx.x & 31;
    float4 h  = *(const float4*)(g_h3 + (size_t)w * FC1 + lane * 4);
    float4 wt = *(const float4*)(Wf2 + lane * 4);
    float s = h.x * wt.x + h.y * wt.y + h.z * wt.z + h.w * wt.w;
#pragma unroll
    for (int off = 16; off; off >>= 1) s += __shfl_xor_sync(0xffffffffu, s, off);
    if (lane == 0) out[w] = s + bf2[0];
}

// ---------------------------------------------------------------------------
// Launch. Inputs identified by element count (proven).
// ---------------------------------------------------------------------------
extern "C" void kernel_launch(void* const* d_in, const int* in_sizes, int n_in,
                              void* d_out, int out_size) {
    const float* z  = nullptr;
    const float* W1 = nullptr, *b1 = nullptr, *W2 = nullptr, *b2 = nullptr;
    const float* Wf1 = nullptr, *bf1 = nullptr, *Wf2 = nullptr, *bf2 = nullptr;
    const void*  ei = nullptr;

    int n49152 = 0, n384 = 0, n128 = 0;
    for (int i = 0; i < n_in; i++) {
        int s = in_sizes[i];
        const void* p = d_in[i];
        switch (s) {
            case 12800000: z  = (const float*)p; break;
            case 3200000:  ei = p;               break;
            case 100000:   break;
            case 147456:   W2 = (const float*)p; break;
            case 49152:
                if (n49152++ == 0) W1 = (const float*)p; else Wf1 = (const float*)p;
                break;
            case 384:
                if (n384++ == 0) b1 = (const float*)p; else b2 = (const float*)p;
                break;
            case 128:
                if (n128++ == 0) bf1 = (const float*)p; else Wf2 = (const float*)p;
                break;
            case 1:        bf2 = (const float*)p; break;
            default: break;
        }
    }
    float* out = (float*)d_out;

    float  *h3;
    __half *h0f, *h1f, *h2f;
    __half *W1h, *W1l, *W2h, *W2l, *Wfh, *Wfl;
    cudaGetSymbolAddress((void**)&h0f, g_h0f);
    cudaGetSymbolAddress((void**)&h1f, g_h1f);
    cudaGetSymbolAddress((void**)&h2f, g_h2f);
    cudaGetSymbolAddress((void**)&h3,  g_h3);
    cudaGetSymbolAddress((void**)&W1h, g_W1h);
    cudaGetSymbolAddress((void**)&W1l, g_W1l);
    cudaGetSymbolAddress((void**)&W2h, g_W2h);
    cudaGetSymbolAddress((void**)&W2l, g_W2l);
    cudaGetSymbolAddress((void**)&Wfh, g_Wfh);
    cudaGetSymbolAddress((void**)&Wfl, g_Wfl);

    cudaFuncSetAttribute(k_gemm2<true , true >, cudaFuncAttributeMaxDynamicSharedMemorySize, SMEM_BYTES);
    cudaFuncSetAttribute(k_gemm2<false, true >, cudaFuncAttributeMaxDynamicSharedMemorySize, SMEM_BYTES);
    cudaFuncSetAttribute(k_gemm2<true , false>, cudaFuncAttributeMaxDynamicSharedMemorySize, SMEM_BYTES);

    // --- weight splits first (hide their launches in the agg chain shadow)
    k_split<<<(IN_C * HID / 4 + 255) / 256, 256>>>(W1,  W1h, W1l, IN_C * HID / 4);
    k_split<<<(HID * HID / 4 + 255) / 256, 256>>>(W2,  W2h, W2l, HID * HID / 4);
    k_split<<<(HID * FC1 / 4 + 255) / 256, 256>>>(Wf1, Wfh, Wfl, HID * FC1 / 4);

    // --- aggregation: detect -> zero -> count -> scan(x3) -> fill -> gather
    k_detect<<<1, 32>>>(ei);
    k_zero  <<<(N_NODES + 256) / 256, 256>>>();
    k_count <<<(N_EDGES + 255) / 256, 256>>>(ei);
    k_scan1 <<<SC_NB, SC_T>>>();
    k_scan2 <<<1, 512>>>();
    k_scan3 <<<SC_NB, SC_T>>>();
    k_fill  <<<(N_EDGES + 255) / 256, 256>>>();
    k_gather<<<(N_NODES * 32 + 255) / 256, 256>>>(z);

    // --- MLP chain (fp16 one-sided split)
    k_gemm2<true , true ><<<dim3(HID / 64, N_PAD / 128), 256, SMEM_BYTES>>>(
        h0f, W1h, W1l, b1, nullptr, h1f, HID, IN_C);
    k_gemm2<false, true ><<<dim3(HID / 64, N_PAD / 128), 256, SMEM_BYTES>>>(
        h1f, W2h, W2l, b2, nullptr, h2f, HID, HID);
    k_gemm2<true , false><<<dim3(FC1 / 64, N_PAD / 128), 256, SMEM_BYTES>>>(
        h2f, Wfh, Wfl, bf1, h3, nullptr, FC1, HID);

    k_out<<<(N_NODES * 32 + 255) / 256, 256>>>(Wf2, bf2, out);
}

// round 17
// speedup vs baseline: 1.4597x; 1.1014x over previous
#include <cuda_runtime.h>
#include <cuda_fp16.h>
#include <cstdint>
#include <cstddef>

// ---------------------------------------------------------------------------
// Problem constants
// ---------------------------------------------------------------------------
#define N_NODES 100000
#define N_PAD   100096              // 782 * 128
#define N_EDGES 1600000
#define IN_C    128
#define HID     384
#define FC1     128

// scan partition
#define SC_T   256
#define SC_NB  ((N_NODES + SC_T - 1) / SC_T)   // 391

// ---------------------------------------------------------------------------
// Scratch (no cudaMalloc allowed). Pad rows of g_h0f are NEVER written ->
// they stay at static zero-init across all graph replays.
// Activations: single fp16 plane. Weights: fp16 hi/lo planes.
// ---------------------------------------------------------------------------
__device__ __half g_h0f[(size_t)N_PAD * IN_C];
__device__ __half g_h1f[(size_t)N_PAD * HID];
__device__ __half g_h2f[(size_t)N_PAD * HID];
__device__ float  g_h3 [(size_t)N_PAD * FC1];
__device__ __half g_W1h[IN_C * HID], g_W1l[IN_C * HID];
__device__ __half g_W2h[HID * HID],  g_W2l[HID * HID];
__device__ __half g_Wfh[HID * FC1],  g_Wfl[HID * FC1];
// CSR scatter->gather machinery
__device__ int    g_srcv[N_EDGES];
__device__ int    g_dstv[N_EDGES];
__device__ int    g_deg[N_NODES + 1];
__device__ int    g_rs [N_NODES + 1];
__device__ int    g_cur[N_NODES];
__device__ int    g_adj[N_EDGES];
__device__ int    g_bsum[SC_NB];
__device__ int    g_boff[SC_NB];
__device__ int    g_is64;

// ---------------------------------------------------------------------------
__device__ __forceinline__ float selu_f(float x) {
    const float sc = 1.0507009873554805f;
    const float al = 1.6732632423543772f;
    return x > 0.f ? sc * x : sc * al * (__expf(x) - 1.f);
}
__device__ __forceinline__ uint32_t s2u(const void* p) {
    return (uint32_t)__cvta_generic_to_shared(p);
}
__device__ __forceinline__ void cp16(void* smem_dst, const void* gmem_src) {
    asm volatile("cp.async.cg.shared.global [%0], [%1], 16;"
                 :: "r"(s2u(smem_dst)), "l"(gmem_src));
}
__device__ __forceinline__ void ldm_x4(uint32_t r[4], uint32_t addr) {
    asm volatile("ldmatrix.sync.aligned.m8n8.x4.shared.b16 {%0,%1,%2,%3}, [%4];"
                 : "=r"(r[0]), "=r"(r[1]), "=r"(r[2]), "=r"(r[3]) : "r"(addr));
}
__device__ __forceinline__ void ldm_x4_t(uint32_t r[4], uint32_t addr) {
    asm volatile("ldmatrix.sync.aligned.m8n8.x4.trans.shared.b16 {%0,%1,%2,%3}, [%4];"
                 : "=r"(r[0]), "=r"(r[1]), "=r"(r[2]), "=r"(r[3]) : "r"(addr));
}
// mma m16n8k16 fp16 -> f32 accumulate
__device__ __forceinline__ void mma_f16(float c[4], const uint32_t a[4],
                                        const uint32_t b0, const uint32_t b1) {
    asm volatile(
        "mma.sync.aligned.m16n8k16.row.col.f32.f16.f16.f32 "
        "{%0,%1,%2,%3}, {%4,%5,%6,%7}, {%8,%9}, {%0,%1,%2,%3};"
        : "+f"(c[0]), "+f"(c[1]), "+f"(c[2]), "+f"(c[3])
        : "r"(a[0]), "r"(a[1]), "r"(a[2]), "r"(a[3]), "r"(b0), "r"(b1));
}

// ---------------------------------------------------------------------------
// edge dtype detect (one warp)
// ---------------------------------------------------------------------------
__global__ void k_detect(const void* __restrict__ ei) {
    const unsigned long long* p = (const unsigned long long*)ei;
    int lane = threadIdx.x;
    int ok = (p[lane] < (unsigned long long)N_NODES) &&
             (p[lane + 32] < (unsigned long long)N_NODES);
    ok = __all_sync(0xffffffffu, ok);
    if (lane == 0) g_is64 = ok;
}

__global__ void k_zero() {
    int i = blockIdx.x * blockDim.x + threadIdx.x;
    if (i <= N_NODES) g_deg[i] = 0;
}

__global__ void k_count(const void* __restrict__ ei) {
    int e = blockIdx.x * blockDim.x + threadIdx.x;
    if (e >= N_EDGES) return;
    long long s, d;
    if (g_is64) {
        const long long* p = (const long long*)ei;
        s = p[e]; d = p[(size_t)N_EDGES + e];
    } else {
        const int* p = (const int*)ei;
        s = p[e]; d = p[(size_t)N_EDGES + e];
    }
    int si = ((unsigned long long)s < N_NODES) ? (int)s : -1;
    int di = ((unsigned long long)d < N_NODES) ? (int)d : -1;
    g_srcv[e] = si;
    g_dstv[e] = di;
    if (si >= 0 && di >= 0) atomicAdd(&g_deg[di], 1);
}

// ---------------------------------------------------------------------------
// 3-phase parallel exclusive scan (proven in R13)
// ---------------------------------------------------------------------------
__global__ void __launch_bounds__(SC_T)
k_scan1() {
    __shared__ int sh[SC_T];
    int idx = blockIdx.x * SC_T + threadIdx.x;
    int v = (idx < N_NODES) ? g_deg[idx] : 0;
    sh[threadIdx.x] = v;
    __syncthreads();
#pragma unroll
    for (int off = SC_T / 2; off > 0; off >>= 1) {
        if (threadIdx.x < off) sh[threadIdx.x] += sh[threadIdx.x + off];
        __syncthreads();
    }
    if (threadIdx.x == 0) g_bsum[blockIdx.x] = sh[0];
}

__global__ void __launch_bounds__(512)
k_scan2() {
    __shared__ int sh[512];
    int t = threadIdx.x;
    int v = (t < SC_NB) ? g_bsum[t] : 0;
    sh[t] = v;
    __syncthreads();
#pragma unroll
    for (int off = 1; off < 512; off <<= 1) {
        int u = (t >= off) ? sh[t - off] : 0;
        __syncthreads();
        sh[t] += u;
        __syncthreads();
    }
    if (t < SC_NB) g_boff[t] = sh[t] - v;
    if (t == 511) g_rs[N_NODES] = sh[511];
}

__global__ void __launch_bounds__(SC_T)
k_scan3() {
    __shared__ int sh[SC_T];
    int idx = blockIdx.x * SC_T + threadIdx.x;
    int v = (idx < N_NODES) ? g_deg[idx] : 0;
    sh[threadIdx.x] = v;
    __syncthreads();
#pragma unroll
    for (int off = 1; off < SC_T; off <<= 1) {
        int u = (threadIdx.x >= off) ? sh[threadIdx.x - off] : 0;
        __syncthreads();
        sh[threadIdx.x] += u;
        __syncthreads();
    }
    if (idx < N_NODES) {
        int r = g_boff[blockIdx.x] + sh[threadIdx.x] - v;
        g_rs[idx]  = r;
        g_cur[idx] = r;
    }
}

__global__ void k_fill() {
    int e = blockIdx.x * blockDim.x + threadIdx.x;
    if (e >= N_EDGES) return;
    int si = g_srcv[e], di = g_dstv[e];
    if (si < 0 || di < 0) return;
    int pos = atomicAdd(&g_cur[di], 1);
    g_adj[pos] = si;
}

// gather: one warp per node; writes h0 single-fp16 plane directly
__global__ void k_gather(const float* __restrict__ z) {
    int w = (blockIdx.x * blockDim.x + threadIdx.x) >> 5;
    if (w >= N_NODES) return;
    int lane = threadIdx.x & 31;

    float4 acc = ((const float4*)(z + (size_t)w * IN_C))[lane];
    int e   = g_rs[w];
    int end = g_rs[w + 1];
    for (; e + 1 < end; e += 2) {
        int s0 = g_adj[e], s1 = g_adj[e + 1];
        float4 v0 = ((const float4*)(z + (size_t)s0 * IN_C))[lane];
        float4 v1 = ((const float4*)(z + (size_t)s1 * IN_C))[lane];
        acc.x += v0.x + v1.x; acc.y += v0.y + v1.y;
        acc.z += v0.z + v1.z; acc.w += v0.w + v1.w;
    }
    if (e < end) {
        int s0 = g_adj[e];
        float4 v0 = ((const float4*)(z + (size_t)s0 * IN_C))[lane];
        acc.x += v0.x; acc.y += v0.y; acc.z += v0.z; acc.w += v0.w;
    }

    size_t o2 = (size_t)w * (IN_C / 2) + lane * 2;   // half2 index
    ((__half2*)g_h0f)[o2]     = __floats2half2_rn(acc.x, acc.y);
    ((__half2*)g_h0f)[o2 + 1] = __floats2half2_rn(acc.z, acc.w);
}

// ---------------------------------------------------------------------------
// weight split fp32 -> (hi, lo) fp16 planes
// ---------------------------------------------------------------------------
__global__ void k_split(const float* __restrict__ X, __half* __restrict__ Xh,
                        __half* __restrict__ Xl, int n4) {
    int i = blockIdx.x * blockDim.x + threadIdx.x;
    if (i >= n4) return;
    float4 v = ((const float4*)X)[i];
    float xs[4] = {v.x, v.y, v.z, v.w};
    __half h[4], l[4];
#pragma unroll
    for (int j = 0; j < 4; j++) {
        h[j] = __float2half_rn(xs[j]);
        l[j] = __float2half_rn(xs[j] - __half2float(h[j]));
    }
    ((__half2*)Xh)[i * 2]     = __halves2half2(h[0], h[1]);
    ((__half2*)Xh)[i * 2 + 1] = __halves2half2(h[2], h[3]);
    ((__half2*)Xl)[i * 2]     = __halves2half2(l[0], l[1]);
    ((__half2*)Xl)[i * 2 + 1] = __halves2half2(l[2], l[3]);
}

// ---------------------------------------------------------------------------
// Pipelined mma.sync GEMM, fp16 one-sided split:
//   C = A(fp16) @ (Bh + Bl) + bias  (+SELU)
// BM=128, BN=128, BK=32; 256 thr = 8 warps (4m x 2n), warp tile 32x64.
// 2-stage cp.async; smem 55.3 KB/CTA -> 2 CTAs/SM.
// ---------------------------------------------------------------------------
#define LDA 40
#define LDB 136
#define OFF_A  0
#define OFF_BH (128 * LDA)                    // 5120
#define OFF_BL (128 * LDA + 32 * LDB)         // 9472
#define STAGE  (128 * LDA + 2 * 32 * LDB)     // 13824 halves
#define SMEM_BYTES (2 * STAGE * 2)            // 55296 B

template <bool DO_SELU, bool OUT_HALF>
__global__ void __launch_bounds__(256, 2)
k_gemm2(const __half* __restrict__ A,
        const __half* __restrict__ Bh, const __half* __restrict__ Bl,
        const float* __restrict__ bias,
        float* __restrict__ C, __half* __restrict__ Ch,
        int N, int K) {
    extern __shared__ __half sm[];

    const int tid  = threadIdx.x;
    const int lane = tid & 31;
    const int wid  = tid >> 5;
    const int wm   = (wid & 3) * 32;      // 4 warps in M
    const int wn   = (wid >> 2) * 64;     // 2 warps in N, 64 cols each
    const int m0   = blockIdx.y * 128;
    const int n0   = blockIdx.x * 128;
    const int NIT  = K / 32;

    auto load_stage = [&](int it, int buf) {
        __half* base = sm + buf * STAGE;
        const int k0 = it * 32;
        // A: 128x32 half = 512 16B-chunks, 2 per thread
#pragma unroll
        for (int t = 0; t < 2; t++) {
            int c = tid + t * 256;
            int row = c >> 2, seg = c & 3;
            cp16(base + OFF_A + row * LDA + seg * 8,
                 A + (size_t)(m0 + row) * K + k0 + seg * 8);
        }
        // B planes: 32x128 half = 512 chunks each; 2/thread per plane
#pragma unroll
        for (int t = 0; t < 2; t++) {
            int c = tid + t * 256;
            int row = c >> 4, seg = c & 15;
            size_t g = (size_t)(k0 + row) * N + n0 + seg * 8;
            int    s = row * LDB + seg * 8;
            cp16(base + OFF_BH + s, Bh + g);
            cp16(base + OFF_BL + s, Bl + g);
        }
        asm volatile("cp.async.commit_group;");
    };

    float acc[2][8][4];
#pragma unroll
    for (int i = 0; i < 2; i++)
#pragma unroll
        for (int j = 0; j < 8; j++)
#pragma unroll
            for (int k = 0; k < 4; k++) acc[i][j][k] = 0.f;

    load_stage(0, 0);

    for (int it = 0; it < NIT; it++) {
        if (it + 1 < NIT) {
            load_stage(it + 1, (it + 1) & 1);
            asm volatile("cp.async.wait_group 1;");
        } else {
            asm volatile("cp.async.wait_group 0;");
        }
        __syncthreads();

        __half* base = sm + (it & 1) * STAGE;
        __half* pA  = base + OFF_A;
        __half* pBh = base + OFF_BH;
        __half* pBl = base + OFF_BL;

#pragma unroll
        for (int kk = 0; kk < 2; kk++) {
            uint32_t a[2][4];
#pragma unroll
            for (int mt = 0; mt < 2; mt++) {
                int row  = wm + mt * 16 + (lane & 15);
                int kofs = kk * 16 + (lane >> 4) * 8;
                ldm_x4(a[mt], s2u(pA + row * LDA + kofs));
            }
#pragma unroll
            for (int ng = 0; ng < 4; ng++) {   // 4 x n16 groups = 64 cols
                uint32_t bh[4], bl[4];
                int krow = kk * 16 + (lane & 15);
                int ncol = wn + ng * 16 + (lane >> 4) * 8;
                ldm_x4_t(bh, s2u(pBh + krow * LDB + ncol));
                ldm_x4_t(bl, s2u(pBl + krow * LDB + ncol));
#pragma unroll
                for (int mt = 0; mt < 2; mt++) {
#pragma unroll
                    for (int nn = 0; nn < 2; nn++) {
                        float* cc = acc[mt][ng * 2 + nn];
                        mma_f16(cc, a[mt], bh[nn * 2], bh[nn * 2 + 1]);
                        mma_f16(cc, a[mt], bl[nn * 2], bl[nn * 2 + 1]);
                    }
                }
            }
        }
        __syncthreads();
    }

    const int rbase = m0 + wm + (lane >> 2);
    const int cbase = n0 + wn + (lane & 3) * 2;
#pragma unroll
    for (int mt = 0; mt < 2; mt++) {
#pragma unroll
        for (int nt = 0; nt < 8; nt++) {
            int row = rbase + mt * 16;
            int col = cbase + nt * 8;
            float b0 = bias[col], b1 = bias[col + 1];
            float v[2][2] = {{acc[mt][nt][0] + b0, acc[mt][nt][1] + b1},
                             {acc[mt][nt][2] + b0, acc[mt][nt][3] + b1}};
#pragma unroll
            for (int r = 0; r < 2; r++) {
                if (DO_SELU) { v[r][0] = selu_f(v[r][0]); v[r][1] = selu_f(v[r][1]); }
                size_t o = (size_t)(row + r * 8) * N + col;
                if (OUT_HALF) {
                    *(__half2*)(Ch + o) = __floats2half2_rn(v[r][0], v[r][1]);
                } else {
                    *(float2*)(C + o) = make_float2(v[r][0], v[r][1]);
                }
            }
        }
    }
}

// ---------------------------------------------------------------------------
// final head
// ---------------------------------------------------------------------------
__global__ void k_out(const float* __restrict__ Wf2,
                      const float* __restrict__ bf2,
                      float* __restrict__ out) {
    int w = (blockIdx.x * blockDim.x + threadIdx.x) >> 5;
    if (w >= N_NODES) return;
    int lane = threadIdx.x & 31;
    float4 h  = *(const float4*)(g_h3 + (size_t)w * FC1 + lane * 4);
    float4 wt = *(const float4*)(Wf2 + lane * 4);
    float s = h.x * wt.x + h.y * wt.y + h.z * wt.z + h.w * wt.w;
#pragma unroll
    for (int off = 16; off; off >>= 1) s += __shfl_xor_sync(0xffffffffu, s, off);
    if (lane == 0) out[w] = s + bf2[0];
}

// ---------------------------------------------------------------------------
// Launch. Inputs identified by element count (proven).
// ---------------------------------------------------------------------------
extern "C" void kernel_launch(void* const* d_in, const int* in_sizes, int n_in,
                              void* d_out, int out_size) {
    const float* z  = nullptr;
    const float* W1 = nullptr, *b1 = nullptr, *W2 = nullptr, *b2 = nullptr;
    const float* Wf1 = nullptr, *bf1 = nullptr, *Wf2 = nullptr, *bf2 = nullptr;
    const void*  ei = nullptr;

    int n49152 = 0, n384 = 0, n128 = 0;
    for (int i = 0; i < n_in; i++) {
        int s = in_sizes[i];
        const void* p = d_in[i];
        switch (s) {
            case 12800000: z  = (const float*)p; break;
            case 3200000:  ei = p;               break;
            case 100000:   break;
            case 147456:   W2 = (const float*)p; break;
            case 49152:
                if (n49152++ == 0) W1 = (const float*)p; else Wf1 = (const float*)p;
                break;
            case 384:
                if (n384++ == 0) b1 = (const float*)p; else b2 = (const float*)p;
                break;
            case 128:
                if (n128++ == 0) bf1 = (const float*)p; else Wf2 = (const float*)p;
                break;
            case 1:        bf2 = (const float*)p; break;
            default: break;
        }
    }
    float* out = (float*)d_out;

    float  *h3;
    __half *h0f, *h1f, *h2f;
    __half *W1h, *W1l, *W2h, *W2l, *Wfh, *Wfl;
    cudaGetSymbolAddress((void**)&h0f, g_h0f);
    cudaGetSymbolAddress((void**)&h1f, g_h1f);
    cudaGetSymbolAddress((void**)&h2f, g_h2f);
    cudaGetSymbolAddress((void**)&h3,  g_h3);
    cudaGetSymbolAddress((void**)&W1h, g_W1h);
    cudaGetSymbolAddress((void**)&W1l, g_W1l);
    cudaGetSymbolAddress((void**)&W2h, g_W2h);
    cudaGetSymbolAddress((void**)&W2l, g_W2l);
    cudaGetSymbolAddress((void**)&Wfh, g_Wfh);
    cudaGetSymbolAddress((void**)&Wfl, g_Wfl);

    cudaFuncSetAttribute(k_gemm2<true , true >, cudaFuncAttributeMaxDynamicSharedMemorySize, SMEM_BYTES);
    cudaFuncSetAttribute(k_gemm2<false, true >, cudaFuncAttributeMaxDynamicSharedMemorySize, SMEM_BYTES);
    cudaFuncSetAttribute(k_gemm2<true , false>, cudaFuncAttributeMaxDynamicSharedMemorySize, SMEM_BYTES);

    // --- weight splits first (hide their launches in the agg chain shadow)
    k_split<<<(IN_C * HID / 4 + 255) / 256, 256>>>(W1,  W1h, W1l, IN_C * HID / 4);
    k_split<<<(HID * HID / 4 + 255) / 256, 256>>>(W2,  W2h, W2l, HID * HID / 4);
    k_split<<<(HID * FC1 / 4 + 255) / 256, 256>>>(Wf1, Wfh, Wfl, HID * FC1 / 4);

    // --- aggregation: detect -> zero -> count -> scan(x3) -> fill -> gather
    k_detect<<<1, 32>>>(ei);
    k_zero  <<<(N_NODES + 256) / 256, 256>>>();
    k_count <<<(N_EDGES + 255) / 256, 256>>>(ei);
    k_scan1 <<<SC_NB, SC_T>>>();
    k_scan2 <<<1, 512>>>();
    k_scan3 <<<SC_NB, SC_T>>>();
    k_fill  <<<(N_EDGES + 255) / 256, 256>>>();
    k_gather<<<(N_NODES * 32 + 255) / 256, 256>>>(z);

    // --- MLP chain (fp16 one-sided split, BN=128)
    k_gemm2<true , true ><<<dim3(HID / 128, N_PAD / 128), 256, SMEM_BYTES>>>(
        h0f, W1h, W1l, b1, nullptr, h1f, HID, IN_C);
    k_gemm2<false, true ><<<dim3(HID / 128, N_PAD / 128), 256, SMEM_BYTES>>>(
        h1f, W2h, W2l, b2, nullptr, h2f, HID, HID);
    k_gemm2<true , false><<<dim3(FC1 / 128, N_PAD / 128), 256, SMEM_BYTES>>>(
        h2f, Wfh, Wfl, bf1, h3, nullptr, FC1, HID);

    k_out<<<(N_NODES * 32 + 255) / 256, 256>>>(Wf2, bf2, out);
}